// round 13
// baseline (speedup 1.0000x reference)
#include <cuda_runtime.h>
#include <math.h>

// Problem constants (fixed by the dataset)
#define NN 8192          // atoms
#define NB 32            // graphs
#define NH 64            // hidden
#define NK 729           // 9^3 lattice points

#define TWO_PI  6.28318530717958647692f
#define FOUR_PI 12.5663706143591729539f

// half-space: lines 40..80 (m_i>0, or m_i==0 && m_j>0, plus (0,0,*) masked to m_z>0)
#define NLINES 41
#define PB     (NN / 64)          // 128 phasor blocks

typedef unsigned long long u64;

// -------- device scratch (no allocations allowed) --------
__device__ float  g_vinv[NB];
__device__ int    g_off[NB + 1];
__device__ float2 g_phas2[27][NN];   // unit phasors e^{i 2pi f_d m}, row (d,m), col atom

// ---------------- packed f32x2 helpers ----------------
__device__ __forceinline__ u64 pk2(float lo, float hi) {
    u64 r; asm("mov.b64 %0,{%1,%2};" : "=l"(r) : "f"(lo), "f"(hi)); return r;
}
__device__ __forceinline__ void upk2(u64 v, float& lo, float& hi) {
    asm("mov.b64 {%0,%1},%2;" : "=f"(lo), "=f"(hi) : "l"(v));
}
__device__ __forceinline__ u64 f2fma(u64 a, u64 b, u64 c) {
    u64 d; asm("fma.rn.f32x2 %0,%1,%2,%3;" : "=l"(d) : "l"(a), "l"(b), "l"(c)); return d;
}
__device__ __forceinline__ u64 f2add(u64 a, u64 b) {
    u64 d; asm("add.rn.f32x2 %0,%1,%2;" : "=l"(d) : "l"(a), "l"(b)); return d;
}
__device__ __forceinline__ u64 f2mul(u64 a, u64 b) {
    u64 d; asm("mul.rn.f32x2 %0,%1,%2;" : "=l"(d) : "l"(a), "l"(b)); return d;
}
__device__ __forceinline__ u64 shx64(u64 v, int m) {
    return __shfl_xor_sync(0xffffffffu, v, m);
}

// ---------------------------------------------------------------------------
// 3x3 inverse (double precision). Returns det.
// ---------------------------------------------------------------------------
__device__ __forceinline__ double inv3x3(const float* c, float* o)
{
    double a = c[0], b = c[1], cc = c[2];
    double d = c[3], e = c[4], f  = c[5];
    double g = c[6], h = c[7], i  = c[8];
    double A  = e * i - f * h;
    double Bv = f * g - d * i;
    double C  = d * h - e * g;
    double det = a * A + b * Bv + cc * C;
    double id = 1.0 / det;
    o[0] = (float)(A * id);
    o[1] = (float)((cc * h - b * i) * id);
    o[2] = (float)((b * f - cc * e) * id);
    o[3] = (float)(Bv * id);
    o[4] = (float)((a * i - cc * g) * id);
    o[5] = (float)((cc * d - a * f) * id);
    o[6] = (float)(C * id);
    o[7] = (float)((b * g - a * h) * id);
    o[8] = (float)((a * e - b * d) * id);
    return det;
}

__device__ __forceinline__ float silu(float a) {
    return __fdividef(a, 1.0f + __expf(-a));
}

// ---------------------------------------------------------------------------
// Prep kernel: per-atom phasors + batch offsets + out-zero + vinv.
// ---------------------------------------------------------------------------
__global__ void __launch_bounds__(64) k_prep(
    const float* __restrict__ pos, const int* __restrict__ batch,
    const float* __restrict__ cell, float* __restrict__ out)
{
    __shared__ float sInv[NB * 9];
    int tid = threadIdx.x;

    if (tid < NB) {
        double det = inv3x3(cell + tid * 9, &sInv[tid * 9]);
        if (blockIdx.x == 0) {
            double vol = fabs(det);
            if (vol < 1e-6) vol = 1e-6;
            g_vinv[tid] = (float)(1.0 / vol);
        }
    }
    __syncthreads();

    int n = blockIdx.x * 64 + tid;
    out[n] = 0.0f;

    int b = batch[n];
    if (n == 0) {
        g_off[0] = 0;
        for (int bb = 1; bb <= b; bb++) g_off[bb] = 0;
    }
    if (n == NN - 1) {
        for (int bb = b + 1; bb <= NB; bb++) g_off[bb] = NN;
    } else {
        int b2 = batch[n + 1];
        for (int bb = b + 1; bb <= b2; bb++) g_off[bb] = n + 1;
    }

    float px = pos[3 * n], py = pos[3 * n + 1], pz = pos[3 * n + 2];
    const float* iv = &sInv[b * 9];
    #pragma unroll
    for (int d = 0; d < 3; d++) {
        float fr = px * iv[d] + py * iv[3 + d] + pz * iv[6 + d];
        float s, c;
        sincosf(TWO_PI * fr, &s, &c);
        float re[9], im[9];
        re[4] = 1.0f; im[4] = 0.0f;
        re[5] = c;    im[5] = s;
        #pragma unroll
        for (int m = 2; m <= 4; m++) {
            re[4 + m] = re[3 + m] * c - im[3 + m] * s;
            im[4 + m] = re[3 + m] * s + im[3 + m] * c;
        }
        #pragma unroll
        for (int m = 1; m <= 4; m++) { re[4 - m] = re[4 + m]; im[4 - m] = -im[4 + m]; }
        #pragma unroll
        for (int mi = 0; mi < 9; mi++) {
            float2 v; v.x = re[mi]; v.y = im[mi];
            g_phas2[d * 9 + mi][n] = v;
        }
    }
}

// ---------------------------------------------------------------------------
// Fused main kernel: 96-thread block per (graph b, half-space line).
// Warps 0,1: split the graph's atoms (pass 1 SF accumulation, exchange
//   reduce, pass 2 energy) — identical to the proven R10 structure.
// Warp 2: computes this block's 9 MLP radial-filter weights CONCURRENTLY with
//   pass 1. Lanes l and l+16 split the 64-input contraction (combined with
//   one xor-16 shuffle); W2 read via uniform __ldg (L1-resident, 16 KB).
// Half-space symmetry factor 2 cancels the 0.5.
// ---------------------------------------------------------------------------
__global__ void __launch_bounds__(96) k_main(
    const float* __restrict__ source, const float* __restrict__ cell,
    const float* __restrict__ W1, const float* __restrict__ B1,
    const float* __restrict__ W2, const float* __restrict__ B2,
    const float* __restrict__ W3, const float* __restrict__ B3,
    float* __restrict__ out)
{
    __shared__ u64 sS[2][36];
    __shared__ float sWz[9];
    __shared__ float sIv[9];

    int b    = blockIdx.x;
    int line = 40 + blockIdx.y;
    int wid  = threadIdx.x >> 5;
    int lane = threadIdx.x & 31;
    int i4 = line / 9, j4 = line % 9;
    int start = g_off[b], end = g_off[b + 1];

    const float2* __restrict__ PX  = g_phas2[i4];
    const float2* __restrict__ PY  = g_phas2[9 + j4];
    const float2* __restrict__ PZ0 = g_phas2[18];      // m_z = -4
    const float2* __restrict__ PZS = g_phas2[23];      // m_z = +1
    const float4* __restrict__ SRC = (const float4*)source;

    if (wid < 2) {
        // =================== atom warps: pass 1 ===================
        u64 acc[36];
        #pragma unroll
        for (int v = 0; v < 36; v++) acc[v] = 0ULL;

        int a = start + lane + 32 * wid;
        float2 LX, LY, LZ0, LZS; float4 LSV;
        if (a < end) { LX = PX[a]; LY = PY[a]; LZ0 = PZ0[a]; LZS = PZS[a]; LSV = SRC[a]; }
        while (a < end) {
            float2 X = LX, Y = LY, Z0 = LZ0, ZS = LZS; float4 sv = LSV;
            int an = a + 64;
            if (an < end) { LX = PX[an]; LY = PY[an]; LZ0 = PZ0[an]; LZS = PZS[an]; LSV = SRC[an]; }
            float c1r = X.x * Y.x - X.y * Y.y;
            float c1i = X.x * Y.y + X.y * Y.x;
            float cr = c1r * Z0.x - c1i * Z0.y;
            float ci = fmaf(c1r, Z0.y, c1i * Z0.x);
            u64 p  = pk2(cr, ci);
            u64 s0 = pk2(sv.x, sv.x), s1 = pk2(sv.y, sv.y);
            u64 s2 = pk2(sv.z, sv.z), s3 = pk2(sv.w, sv.w);
            #pragma unroll
            for (int z = 0; z < 9; z++) {
                acc[z * 4 + 0] = f2fma(s0, p, acc[z * 4 + 0]);
                acc[z * 4 + 1] = f2fma(s1, p, acc[z * 4 + 1]);
                acc[z * 4 + 2] = f2fma(s2, p, acc[z * 4 + 2]);
                acc[z * 4 + 3] = f2fma(s3, p, acc[z * 4 + 3]);
                if (z < 8) {
                    float t = cr * ZS.x - ci * ZS.y;
                    ci = fmaf(cr, ZS.y, ci * ZS.x);
                    cr = t;
                    p = pk2(cr, ci);
                }
            }
            a = an;
        }

        // distributed exchange reduce on acc[0..31]: lane l ends with value l
        #pragma unroll
        for (int o = 16; o >= 1; o >>= 1) {
            bool hi = (lane & o) != 0;
            #pragma unroll
            for (int j = 0; j < o; j++) {
                u64 tlo = shx64(acc[j],     o);
                u64 thi = shx64(acc[j + o], o);
                acc[j] = hi ? f2add(acc[j + o], thi) : f2add(acc[j], tlo);
            }
        }
        sS[wid][lane] = acc[0];
        // tail values 32..35 (z=8): full butterfly
        #pragma unroll
        for (int o = 16; o; o >>= 1) {
            acc[32] = f2add(acc[32], shx64(acc[32], o));
            acc[33] = f2add(acc[33], shx64(acc[33], o));
            acc[34] = f2add(acc[34], shx64(acc[34], o));
            acc[35] = f2add(acc[35], shx64(acc[35], o));
        }
        if (lane < 4) {
            u64 qv = (lane == 0) ? acc[32] : (lane == 1) ? acc[33]
                   : (lane == 2) ? acc[34] : acc[35];
            sS[wid][32 + lane] = qv;
        }
    } else {
        // =================== MLP warp (overlaps pass 1) ===================
        if (lane == 0) inv3x3(cell + b * 9, sIv);
        __syncwarp();

        int zi = lane & 15; if (zi > 8) zi = 8;   // lanes 9..15 / 25..31 duplicate z=8
        int ih = lane >> 4;                        // input half
        int ki = i4 - 4, kj = j4 - 4, kk = zi - 4;
        float kc0 = TWO_PI * ((float)ki * sIv[0] + (float)kj * sIv[3] + (float)kk * sIv[6]);
        float kc1 = TWO_PI * ((float)ki * sIv[1] + (float)kj * sIv[4] + (float)kk * sIv[7]);
        float kc2 = TWO_PI * ((float)ki * sIv[2] + (float)kj * sIv[5] + (float)kk * sIv[8]);
        float kn = sqrtf(kc0 * kc0 + kc1 * kc1 + kc2 * kc2);
        float safe = fmaxf(kn, 1e-6f);
        float x0 = log1pf(safe);
        float f0 = x0, f1 = x0 * x0, f2 = 1.0f / safe;

        // layer 1 fused into layer 2: acc[q] = partial of outputs (2q, 2q+1)
        u64 acc[32];
        #pragma unroll
        for (int q = 0; q < 32; q++) acc[q] = 0ULL;
        const u64* __restrict__ W2v = (const u64*)W2;   // 32 u64 per row of 64 floats
        int i0 = ih * 32;
        #pragma unroll 4
        for (int t = 0; t < 32; t++) {
            int i = i0 + t;
            float av = __ldg(B1 + i) + f0 * __ldg(W1 + i)
                     + f1 * __ldg(W1 + NH + i) + f2 * __ldg(W1 + 2 * NH + i);
            float h = silu(av);
            u64 hp = pk2(h, h);
            const u64* row = W2v + i * 32;             // FIXED: 32 u64 row stride
            #pragma unroll
            for (int q = 0; q < 32; q += 2) {
                ulonglong2 wv = __ldg((const ulonglong2*)(row + q));
                acc[q]     = f2fma(hp, wv.x, acc[q]);
                acc[q + 1] = f2fma(hp, wv.y, acc[q + 1]);
            }
        }
        // combine the two input-halves (lane l <-> l+16)
        #pragma unroll
        for (int q = 0; q < 32; q++) acc[q] = f2add(acc[q], shx64(acc[q], 16));

        float o = __ldg(B3);
        #pragma unroll
        for (int q = 0; q < 32; q++) {
            float p0, p1; upk2(acc[q], p0, p1);
            float h20 = silu(p0 + __ldg(B2 + 2 * q));
            float h21 = silu(p1 + __ldg(B2 + 2 * q + 1));
            o = fmaf(h20, __ldg(W3 + 2 * q), fmaf(h21, __ldg(W3 + 2 * q + 1), o));
        }
        float sp = (o > 80.0f) ? o : log1pf(__expf(o));
        bool active = (kn > 1e-6f) && !(line == 40 && zi < 4);
        float w = active ? (FOUR_PI / (safe * safe)) * sp : 0.0f;
        if (lane < 9) sWz[lane] = w;
    }
    __syncthreads();

    if (wid >= 2) return;

    // ---- combine atom-halves + fold in w(k) ----
    int peer = wid ^ 1;
    u64 Wp[36];
    #pragma unroll
    for (int z = 0; z < 9; z++) {
        float wzv = sWz[z];
        u64 wzp = pk2(wzv, wzv);
        #pragma unroll
        for (int c = 0; c < 4; c++) {
            int v = z * 4 + c;
            Wp[v] = f2mul(wzp, f2add(sS[wid][v], sS[peer][v]));
        }
    }
    float hv = g_vinv[b];   // 0.5 (energy) x 2 (half-space) = 1

    // ---- pass 2: per-atom energy from this line's 9 k's ----
    {
        int a = start + lane + 32 * wid;
        float2 LX, LY, LZ0, LZS; float4 LSV;
        if (a < end) { LX = PX[a]; LY = PY[a]; LZ0 = PZ0[a]; LZS = PZS[a]; LSV = SRC[a]; }
        while (a < end) {
            float2 X = LX, Y = LY, Z0 = LZ0, ZS = LZS; float4 sv = LSV;
            int an = a + 64;
            if (an < end) { LX = PX[an]; LY = PY[an]; LZ0 = PZ0[an]; LZS = PZS[an]; LSV = SRC[an]; }
            float c1r = X.x * Y.x - X.y * Y.y;
            float c1i = X.x * Y.y + X.y * Y.x;
            float cr = c1r * Z0.x - c1i * Z0.y;
            float ci = fmaf(c1r, Z0.y, c1i * Z0.x);
            u64 p = pk2(cr, ci);
            u64 E0 = 0ULL, E1 = 0ULL, E2 = 0ULL, E3 = 0ULL;
            #pragma unroll
            for (int z = 0; z < 9; z++) {
                E0 = f2fma(p, Wp[z * 4 + 0], E0);
                E1 = f2fma(p, Wp[z * 4 + 1], E1);
                E2 = f2fma(p, Wp[z * 4 + 2], E2);
                E3 = f2fma(p, Wp[z * 4 + 3], E3);
                if (z < 8) {
                    float t = cr * ZS.x - ci * ZS.y;
                    ci = fmaf(cr, ZS.y, ci * ZS.x);
                    cr = t;
                    p = pk2(cr, ci);
                }
            }
            float e0a, e0b, e1a, e1b, e2a, e2b, e3a, e3b;
            upk2(E0, e0a, e0b); upk2(E1, e1a, e1b);
            upk2(E2, e2a, e2b); upk2(E3, e3a, e3b);
            float e = sv.x * (e0a + e0b) + sv.y * (e1a + e1b)
                    + sv.z * (e2a + e2b) + sv.w * (e3a + e3b);
            atomicAdd(out + a, hv * e);
            a = an;
        }
    }
}

// ---------------------------------------------------------------------------
extern "C" void kernel_launch(void* const* d_in, const int* in_sizes, int n_in,
                              void* d_out, int out_size)
{
    const float* pos    = (const float*)d_in[0];
    const int*   batch  = (const int*)d_in[1];
    const float* cell   = (const float*)d_in[2];
    const float* source = (const float*)d_in[3];
    const float* W1 = (const float*)d_in[4];
    const float* B1 = (const float*)d_in[5];
    const float* W2 = (const float*)d_in[6];
    const float* B2 = (const float*)d_in[7];
    const float* W3 = (const float*)d_in[8];
    const float* B3 = (const float*)d_in[9];
    float* out = (float*)d_out;

    k_prep<<<PB, 64>>>(pos, batch, cell, out);
    k_main<<<dim3(NB, NLINES), 96>>>(source, cell, W1, B1, W2, B2, W3, B3, out);
}

// round 14
// speedup vs baseline: 1.7105x; 1.7105x over previous
#include <cuda_runtime.h>
#include <math.h>

// Problem constants (fixed by the dataset)
#define NN 8192          // atoms
#define NB 32            // graphs
#define NH 64            // hidden
#define NK 729           // 9^3 lattice points

#define TWO_PI  6.28318530717958647692f
#define FOUR_PI 12.5663706143591729539f

// half-space: lines 40..80 (m_i>0, or m_i==0 && m_j>0, plus (0,0,*) masked to m_z>0)
#define NLINES   41
#define NW_ITEMS (NB * NLINES * 9)          // 11808
#define WB ((NW_ITEMS + 63) / 64)           // 185 MLP blocks (launched first)
#define PB (NN / 64)                        // 128 phasor blocks

typedef unsigned long long u64;

// -------- device scratch (no allocations allowed) --------
__device__ float  g_vinv[NB];
__device__ int    g_off[NB + 1];
__device__ float  g_w[NB][NK];
__device__ float2 g_phas2[27][NN];   // unit phasors e^{i 2pi f_d m}, row (d,m), col atom

// ---------------- packed f32x2 helpers ----------------
__device__ __forceinline__ u64 pk2(float lo, float hi) {
    u64 r; asm("mov.b64 %0,{%1,%2};" : "=l"(r) : "f"(lo), "f"(hi)); return r;
}
__device__ __forceinline__ void upk2(u64 v, float& lo, float& hi) {
    asm("mov.b64 {%0,%1},%2;" : "=f"(lo), "=f"(hi) : "l"(v));
}
__device__ __forceinline__ u64 f2fma(u64 a, u64 b, u64 c) {
    u64 d; asm("fma.rn.f32x2 %0,%1,%2,%3;" : "=l"(d) : "l"(a), "l"(b), "l"(c)); return d;
}
__device__ __forceinline__ u64 f2add(u64 a, u64 b) {
    u64 d; asm("add.rn.f32x2 %0,%1,%2;" : "=l"(d) : "l"(a), "l"(b)); return d;
}
__device__ __forceinline__ u64 f2mul(u64 a, u64 b) {
    u64 d; asm("mul.rn.f32x2 %0,%1,%2;" : "=l"(d) : "l"(a), "l"(b)); return d;
}
__device__ __forceinline__ u64 shx64(u64 v, int m) {
    return __shfl_xor_sync(0xffffffffu, v, m);
}

// ---------------------------------------------------------------------------
// 3x3 inverse (double precision). Returns det.
// ---------------------------------------------------------------------------
__device__ __forceinline__ double inv3x3(const float* c, float* o)
{
    double a = c[0], b = c[1], cc = c[2];
    double d = c[3], e = c[4], f  = c[5];
    double g = c[6], h = c[7], i  = c[8];
    double A  = e * i - f * h;
    double Bv = f * g - d * i;
    double C  = d * h - e * g;
    double det = a * A + b * Bv + cc * C;
    double id = 1.0 / det;
    o[0] = (float)(A * id);
    o[1] = (float)((cc * h - b * i) * id);
    o[2] = (float)((b * f - cc * e) * id);
    o[3] = (float)(Bv * id);
    o[4] = (float)((a * i - cc * g) * id);
    o[5] = (float)((cc * d - a * f) * id);
    o[6] = (float)(C * id);
    o[7] = (float)((b * g - a * h) * id);
    o[8] = (float)((a * e - b * d) * id);
    return det;
}

__device__ __forceinline__ float silu(float a) {
    return __fdividef(a, 1.0f + __expf(-a));
}

// ---------------------------------------------------------------------------
// Build the 9 packed phases P[z] = c1 * z^(z-4) from c1 and zs = e^{i*2pi*fz}.
// Chain depth 2 (z2 from z1; z3,z4 from z2), then all +/-m pairs via shared
// products with conj symmetry: z^-m = conj(z^m).  All pairs independent.
// ---------------------------------------------------------------------------
__device__ __forceinline__ void build_phases(
    float c1r, float c1i, float z1r, float z1i, u64* P)
{
    float z2r = z1r * z1r - z1i * z1i, z2i = 2.0f * z1r * z1i;
    float z3r = z2r * z1r - z2i * z1i, z3i = fmaf(z2r, z1i, z2i * z1r);
    float z4r = z2r * z2r - z2i * z2i, z4i = 2.0f * z2r * z2i;
    P[4] = pk2(c1r, c1i);
    {
        float t1 = c1r * z1r, t2 = c1i * z1i, t3 = c1r * z1i, t4 = c1i * z1r;
        P[5] = pk2(t1 - t2, t3 + t4);
        P[3] = pk2(t1 + t2, t4 - t3);
    }
    {
        float t1 = c1r * z2r, t2 = c1i * z2i, t3 = c1r * z2i, t4 = c1i * z2r;
        P[6] = pk2(t1 - t2, t3 + t4);
        P[2] = pk2(t1 + t2, t4 - t3);
    }
    {
        float t1 = c1r * z3r, t2 = c1i * z3i, t3 = c1r * z3i, t4 = c1i * z3r;
        P[7] = pk2(t1 - t2, t3 + t4);
        P[1] = pk2(t1 + t2, t4 - t3);
    }
    {
        float t1 = c1r * z4r, t2 = c1i * z4i, t3 = c1r * z4i, t4 = c1i * z4r;
        P[8] = pk2(t1 - t2, t3 + t4);
        P[0] = pk2(t1 + t2, t4 - t3);
    }
}

// ---------------------------------------------------------------------------
// Fused prep kernel. Blocks [0,WB): MLP radial filter (half-space).
// Blocks [WB,WB+PB): per-atom phasors + batch offsets + out-zero.
// (Proven R10 structure.)
// ---------------------------------------------------------------------------
__global__ void __launch_bounds__(64) k_prep(
    const float* __restrict__ pos, const int* __restrict__ batch,
    const float* __restrict__ cell,
    const float* __restrict__ W1, const float* __restrict__ B1,
    const float* __restrict__ W2, const float* __restrict__ B2,
    const float* __restrict__ W3, const float* __restrict__ B3,
    float* __restrict__ out)
{
    __shared__ float sInv[NB * 9];
    __shared__ __align__(16) float sW2T[NH * 72];   // row j padded to 72 floats
    __shared__ float sW1[3 * NH], sB1[NH], sB2[NH], sW3[NH];

    int tid = threadIdx.x;

    if (tid < NB) {
        double det = inv3x3(cell + tid * 9, &sInv[tid * 9]);
        if (blockIdx.x == 0) {
            double vol = fabs(det);
            if (vol < 1e-6) vol = 1e-6;
            g_vinv[tid] = (float)(1.0 / vol);
        }
    }

    if (blockIdx.x < WB) {
        // ---------------- MLP role ----------------
        for (int idx = tid; idx < 3 * NH; idx += 64) sW1[idx] = W1[idx];
        for (int idx = tid; idx < NH; idx += 64) {
            sB1[idx] = B1[idx]; sB2[idx] = B2[idx]; sW3[idx] = W3[idx];
        }
        for (int idx = tid; idx < NH * NH; idx += 64) {
            int i = idx >> 6, j = idx & 63;
            sW2T[j * 72 + i] = W2[idx];
        }
        __syncthreads();

        int g = blockIdx.x * 64 + tid;
        if (g >= NW_ITEMS) return;
        int b    = g / (NLINES * 9);
        int rem  = g - b * (NLINES * 9);
        int line = 40 + rem / 9;
        int z    = rem % 9;
        int ki = line / 9 - 4;
        int kj = line % 9 - 4;
        int kk = z - 4;
        const float* iv = &sInv[b * 9];
        float kc0 = TWO_PI * ((float)ki * iv[0] + (float)kj * iv[3] + (float)kk * iv[6]);
        float kc1 = TWO_PI * ((float)ki * iv[1] + (float)kj * iv[4] + (float)kk * iv[7]);
        float kc2 = TWO_PI * ((float)ki * iv[2] + (float)kj * iv[5] + (float)kk * iv[8]);
        float kn = sqrtf(kc0 * kc0 + kc1 * kc1 + kc2 * kc2);

        float w = 0.0f;
        bool active = (kn > 1e-6f) && !(line == 40 && z < 4);   // half-space mask
        if (active) {
            float x0 = log1pf(kn);
            float f0 = x0, f1 = x0 * x0, f2 = 1.0f / kn;
            u64 h1p[NH / 2];
            #pragma unroll
            for (int j = 0; j < NH; j += 2) {
                float a0 = fmaf(f0, sW1[j],     fmaf(f1, sW1[NH + j],     fmaf(f2, sW1[2 * NH + j],     sB1[j])));
                float a1 = fmaf(f0, sW1[j + 1], fmaf(f1, sW1[NH + j + 1], fmaf(f2, sW1[2 * NH + j + 1], sB1[j + 1])));
                h1p[j >> 1] = pk2(silu(a0), silu(a1));
            }
            float o = B3[0];
            for (int j = 0; j < NH; j++) {
                const ulonglong2* wr = (const ulonglong2*)&sW2T[j * 72];
                u64 acc0 = pk2(sB2[j], 0.0f);
                u64 acc1 = 0ULL;
                #pragma unroll
                for (int i2 = 0; i2 < 16; i2++) {
                    ulonglong2 wv = wr[i2];
                    acc0 = f2fma(h1p[2 * i2],     wv.x, acc0);
                    acc1 = f2fma(h1p[2 * i2 + 1], wv.y, acc1);
                }
                float p0, p1, q0, q1;
                upk2(acc0, p0, p1); upk2(acc1, q0, q1);
                float a = (p0 + p1) + (q0 + q1);
                o = fmaf(silu(a), sW3[j], o);
            }
            float sp = (o > 80.0f) ? o : log1pf(__expf(o));       // softplus
            w = (FOUR_PI / (kn * kn)) * sp;
        }
        g_w[b][line * 9 + z] = w;
    } else {
        // ---------------- phasor role ----------------
        __syncthreads();
        int n = (blockIdx.x - WB) * 64 + tid;
        out[n] = 0.0f;

        int b = batch[n];
        if (n == 0) {
            g_off[0] = 0;
            for (int bb = 1; bb <= b; bb++) g_off[bb] = 0;
        }
        if (n == NN - 1) {
            for (int bb = b + 1; bb <= NB; bb++) g_off[bb] = NN;
        } else {
            int b2 = batch[n + 1];
            for (int bb = b + 1; bb <= b2; bb++) g_off[bb] = n + 1;
        }

        float px = pos[3 * n], py = pos[3 * n + 1], pz = pos[3 * n + 2];
        const float* iv = &sInv[b * 9];
        #pragma unroll
        for (int d = 0; d < 3; d++) {
            float fr = px * iv[d] + py * iv[3 + d] + pz * iv[6 + d];
            float s, c;
            sincosf(TWO_PI * fr, &s, &c);
            float re[9], im[9];
            re[4] = 1.0f; im[4] = 0.0f;
            re[5] = c;    im[5] = s;
            #pragma unroll
            for (int m = 2; m <= 4; m++) {
                re[4 + m] = re[3 + m] * c - im[3 + m] * s;
                im[4 + m] = re[3 + m] * s + im[3 + m] * c;
            }
            #pragma unroll
            for (int m = 1; m <= 4; m++) { re[4 - m] = re[4 + m]; im[4 - m] = -im[4 + m]; }
            #pragma unroll
            for (int mi = 0; mi < 9; mi++) {
                float2 v; v.x = re[mi]; v.y = im[mi];
                g_phas2[d * 9 + mi][n] = v;
            }
        }
    }
}

// ---------------------------------------------------------------------------
// Fused main kernel: 64-thread block per (graph b, half-space line).
// Two warps split the atom range (R10-proven structure). Phase generation
// uses the conj-symmetric scheme: chain depth 2 instead of 8, no Z0 stream.
// Half-space symmetry factor 2 cancels the 0.5.
// ---------------------------------------------------------------------------
__global__ void __launch_bounds__(64) k_main(const float* __restrict__ source,
                                             float* __restrict__ out)
{
    __shared__ u64 sS[2][36];

    int b    = blockIdx.x;
    int line = 40 + blockIdx.y;
    int w    = threadIdx.x >> 5;
    int lane = threadIdx.x & 31;
    int i4 = line / 9, j4 = line % 9;
    int start = g_off[b], end = g_off[b + 1];

    const float2* __restrict__ PX  = g_phas2[i4];
    const float2* __restrict__ PY  = g_phas2[9 + j4];
    const float2* __restrict__ PZS = g_phas2[23];      // m_z = +1
    const float4* __restrict__ SRC = (const float4*)source;

    u64 acc[36];            // packed (SC, SS) partials, index v = z*4 + c
    #pragma unroll
    for (int v = 0; v < 36; v++) acc[v] = 0ULL;

    // ---- pass 1: structure factors (this warp's atom share) ----
    {
        int a = start + lane + 32 * w;
        float2 LX, LY, LZS; float4 LSV;
        if (a < end) { LX = PX[a]; LY = PY[a]; LZS = PZS[a]; LSV = SRC[a]; }
        while (a < end) {
            float2 X = LX, Y = LY, ZS = LZS; float4 sv = LSV;
            int an = a + 64;
            if (an < end) { LX = PX[an]; LY = PY[an]; LZS = PZS[an]; LSV = SRC[an]; }
            float c1r = X.x * Y.x - X.y * Y.y;
            float c1i = X.x * Y.y + X.y * Y.x;
            u64 P[9];
            build_phases(c1r, c1i, ZS.x, ZS.y, P);
            u64 s0 = pk2(sv.x, sv.x), s1 = pk2(sv.y, sv.y);
            u64 s2 = pk2(sv.z, sv.z), s3 = pk2(sv.w, sv.w);
            #pragma unroll
            for (int z = 0; z < 9; z++) {
                acc[z * 4 + 0] = f2fma(s0, P[z], acc[z * 4 + 0]);
                acc[z * 4 + 1] = f2fma(s1, P[z], acc[z * 4 + 1]);
                acc[z * 4 + 2] = f2fma(s2, P[z], acc[z * 4 + 2]);
                acc[z * 4 + 3] = f2fma(s3, P[z], acc[z * 4 + 3]);
            }
            a = an;
        }
    }

    // ---- distributed exchange reduce on acc[0..31]: lane l ends with value l ----
    #pragma unroll
    for (int o = 16; o >= 1; o >>= 1) {
        bool hi = (lane & o) != 0;
        #pragma unroll
        for (int j = 0; j < o; j++) {
            u64 tlo = shx64(acc[j],     o);
            u64 thi = shx64(acc[j + o], o);
            acc[j] = hi ? f2add(acc[j + o], thi) : f2add(acc[j], tlo);
        }
    }
    sS[w][lane] = acc[0];
    // tail values 32..35 (z=8): full butterfly, all lanes end with totals
    #pragma unroll
    for (int o = 16; o; o >>= 1) {
        acc[32] = f2add(acc[32], shx64(acc[32], o));
        acc[33] = f2add(acc[33], shx64(acc[33], o));
        acc[34] = f2add(acc[34], shx64(acc[34], o));
        acc[35] = f2add(acc[35], shx64(acc[35], o));
    }
    if (lane < 4) {
        u64 qv = (lane == 0) ? acc[32] : (lane == 1) ? acc[33]
               : (lane == 2) ? acc[34] : acc[35];
        sS[w][32 + lane] = qv;
    }
    __syncthreads();

    // ---- combine the two warps + fold in w(k): Wp[v] = wz * (S0[v] + S1[v]) ----
    u64 Wp[36];
    #pragma unroll
    for (int z = 0; z < 9; z++) {
        float wzv = g_w[b][line * 9 + z];
        u64 wzp = pk2(wzv, wzv);
        #pragma unroll
        for (int c = 0; c < 4; c++) {
            int v = z * 4 + c;
            Wp[v] = f2mul(wzp, f2add(sS[0][v], sS[1][v]));
        }
    }
    float hv = g_vinv[b];   // 0.5 (energy) x 2 (half-space) = 1

    // ---- pass 2: per-atom energy from this line's 9 k's ----
    {
        int a = start + lane + 32 * w;
        float2 LX, LY, LZS; float4 LSV;
        if (a < end) { LX = PX[a]; LY = PY[a]; LZS = PZS[a]; LSV = SRC[a]; }
        while (a < end) {
            float2 X = LX, Y = LY, ZS = LZS; float4 sv = LSV;
            int an = a + 64;
            if (an < end) { LX = PX[an]; LY = PY[an]; LZS = PZS[an]; LSV = SRC[an]; }
            float c1r = X.x * Y.x - X.y * Y.y;
            float c1i = X.x * Y.y + X.y * Y.x;
            u64 P[9];
            build_phases(c1r, c1i, ZS.x, ZS.y, P);
            u64 E0 = 0ULL, E1 = 0ULL, E2 = 0ULL, E3 = 0ULL;
            #pragma unroll
            for (int z = 0; z < 9; z++) {
                E0 = f2fma(P[z], Wp[z * 4 + 0], E0);
                E1 = f2fma(P[z], Wp[z * 4 + 1], E1);
                E2 = f2fma(P[z], Wp[z * 4 + 2], E2);
                E3 = f2fma(P[z], Wp[z * 4 + 3], E3);
            }
            float e0a, e0b, e1a, e1b, e2a, e2b, e3a, e3b;
            upk2(E0, e0a, e0b); upk2(E1, e1a, e1b);
            upk2(E2, e2a, e2b); upk2(E3, e3a, e3b);
            float e = sv.x * (e0a + e0b) + sv.y * (e1a + e1b)
                    + sv.z * (e2a + e2b) + sv.w * (e3a + e3b);
            atomicAdd(out + a, hv * e);
            a = an;
        }
    }
}

// ---------------------------------------------------------------------------
extern "C" void kernel_launch(void* const* d_in, const int* in_sizes, int n_in,
                              void* d_out, int out_size)
{
    const float* pos    = (const float*)d_in[0];
    const int*   batch  = (const int*)d_in[1];
    const float* cell   = (const float*)d_in[2];
    const float* source = (const float*)d_in[3];
    const float* W1 = (const float*)d_in[4];
    const float* B1 = (const float*)d_in[5];
    const float* W2 = (const float*)d_in[6];
    const float* B2 = (const float*)d_in[7];
    const float* W3 = (const float*)d_in[8];
    const float* B3 = (const float*)d_in[9];
    float* out = (float*)d_out;

    k_prep<<<WB + PB, 64>>>(pos, batch, cell, W1, B1, W2, B2, W3, B3, out);
    k_main<<<dim3(NB, NLINES), 64>>>(source, out);
}

// round 15
// speedup vs baseline: 1.7411x; 1.0179x over previous
#include <cuda_runtime.h>
#include <math.h>

// Problem constants (fixed by the dataset)
#define NN 8192          // atoms
#define NB 32            // graphs
#define NH 64            // hidden
#define NK 729           // 9^3 lattice points

#define TWO_PI  6.28318530717958647692f
#define FOUR_PI 12.5663706143591729539f

// half-space: lines 40..80 (m_i>0, or m_i==0 && m_j>0, plus (0,0,*) masked to m_z>0)
#define NLINES   41
#define NW_ITEMS (NB * NLINES * 9)          // 11808
#define WB ((NW_ITEMS + 63) / 64)           // 185 MLP blocks (64 items x 2 threads each)
#define PB (NN / 128)                       // 64 phasor blocks

typedef unsigned long long u64;

// -------- device scratch (no allocations allowed) --------
__device__ float  g_vinv[NB];
__device__ int    g_off[NB + 1];
__device__ float  g_w[NB][NK];
__device__ float2 g_phas2[27][NN];   // unit phasors e^{i 2pi f_d m}, row (d,m), col atom

// ---------------- packed f32x2 helpers ----------------
__device__ __forceinline__ u64 pk2(float lo, float hi) {
    u64 r; asm("mov.b64 %0,{%1,%2};" : "=l"(r) : "f"(lo), "f"(hi)); return r;
}
__device__ __forceinline__ void upk2(u64 v, float& lo, float& hi) {
    asm("mov.b64 {%0,%1},%2;" : "=f"(lo), "=f"(hi) : "l"(v));
}
__device__ __forceinline__ u64 f2fma(u64 a, u64 b, u64 c) {
    u64 d; asm("fma.rn.f32x2 %0,%1,%2,%3;" : "=l"(d) : "l"(a), "l"(b), "l"(c)); return d;
}
__device__ __forceinline__ u64 f2add(u64 a, u64 b) {
    u64 d; asm("add.rn.f32x2 %0,%1,%2;" : "=l"(d) : "l"(a), "l"(b)); return d;
}
__device__ __forceinline__ u64 f2mul(u64 a, u64 b) {
    u64 d; asm("mul.rn.f32x2 %0,%1,%2;" : "=l"(d) : "l"(a), "l"(b)); return d;
}
__device__ __forceinline__ u64 shx64(u64 v, int m) {
    return __shfl_xor_sync(0xffffffffu, v, m);
}

// ---------------------------------------------------------------------------
// 3x3 inverse (double precision). Returns det.
// ---------------------------------------------------------------------------
__device__ __forceinline__ double inv3x3(const float* c, float* o)
{
    double a = c[0], b = c[1], cc = c[2];
    double d = c[3], e = c[4], f  = c[5];
    double g = c[6], h = c[7], i  = c[8];
    double A  = e * i - f * h;
    double Bv = f * g - d * i;
    double C  = d * h - e * g;
    double det = a * A + b * Bv + cc * C;
    double id = 1.0 / det;
    o[0] = (float)(A * id);
    o[1] = (float)((cc * h - b * i) * id);
    o[2] = (float)((b * f - cc * e) * id);
    o[3] = (float)(Bv * id);
    o[4] = (float)((a * i - cc * g) * id);
    o[5] = (float)((cc * d - a * f) * id);
    o[6] = (float)(C * id);
    o[7] = (float)((b * g - a * h) * id);
    o[8] = (float)((a * e - b * d) * id);
    return det;
}

__device__ __forceinline__ float silu(float a) {
    return __fdividef(a, 1.0f + __expf(-a));
}

// ---------------------------------------------------------------------------
// Build the 9 packed phases P[z] = c1 * z^(z-4) from c1 and z1 = e^{i*2pi*fz}.
// Chain depth 2; all +/-m pairs via conj symmetry, fully independent.
// ---------------------------------------------------------------------------
__device__ __forceinline__ void build_phases(
    float c1r, float c1i, float z1r, float z1i, u64* P)
{
    float z2r = z1r * z1r - z1i * z1i, z2i = 2.0f * z1r * z1i;
    float z3r = z2r * z1r - z2i * z1i, z3i = fmaf(z2r, z1i, z2i * z1r);
    float z4r = z2r * z2r - z2i * z2i, z4i = 2.0f * z2r * z2i;
    P[4] = pk2(c1r, c1i);
    {
        float t1 = c1r * z1r, t2 = c1i * z1i, t3 = c1r * z1i, t4 = c1i * z1r;
        P[5] = pk2(t1 - t2, t3 + t4);
        P[3] = pk2(t1 + t2, t4 - t3);
    }
    {
        float t1 = c1r * z2r, t2 = c1i * z2i, t3 = c1r * z2i, t4 = c1i * z2r;
        P[6] = pk2(t1 - t2, t3 + t4);
        P[2] = pk2(t1 + t2, t4 - t3);
    }
    {
        float t1 = c1r * z3r, t2 = c1i * z3i, t3 = c1r * z3i, t4 = c1i * z3r;
        P[7] = pk2(t1 - t2, t3 + t4);
        P[1] = pk2(t1 + t2, t4 - t3);
    }
    {
        float t1 = c1r * z4r, t2 = c1i * z4i, t3 = c1r * z4i, t4 = c1i * z4r;
        P[8] = pk2(t1 - t2, t3 + t4);
        P[0] = pk2(t1 + t2, t4 - t3);
    }
}

// ---------------------------------------------------------------------------
// Fused prep kernel (128 threads). Blocks [0,WB): MLP radial filter,
// 2 threads per item (j-split of layer 2). Blocks [WB,WB+PB): per-atom
// phasors + batch offsets + out-zero.
// ---------------------------------------------------------------------------
__global__ void __launch_bounds__(128) k_prep(
    const float* __restrict__ pos, const int* __restrict__ batch,
    const float* __restrict__ cell,
    const float* __restrict__ W1, const float* __restrict__ B1,
    const float* __restrict__ W2, const float* __restrict__ B2,
    const float* __restrict__ W3, const float* __restrict__ B3,
    float* __restrict__ out)
{
    __shared__ float sInv[NB * 9];
    __shared__ __align__(16) float sW2T[NH * 72];   // row j padded to 72 floats
    __shared__ float sW1[3 * NH], sB1[NH], sB2[NH], sW3[NH];

    int tid = threadIdx.x;

    if (tid < NB) {
        double det = inv3x3(cell + tid * 9, &sInv[tid * 9]);
        if (blockIdx.x == 0) {
            double vol = fabs(det);
            if (vol < 1e-6) vol = 1e-6;
            g_vinv[tid] = (float)(1.0 / vol);
        }
    }

    if (blockIdx.x < WB) {
        // ---------------- MLP role: 2 threads per item ----------------
        for (int idx = tid; idx < 3 * NH; idx += 128) sW1[idx] = W1[idx];
        for (int idx = tid; idx < NH; idx += 128) {
            sB1[idx] = B1[idx]; sB2[idx] = B2[idx]; sW3[idx] = W3[idx];
        }
        for (int idx = tid; idx < NH * NH; idx += 128) {
            int i = idx >> 6, j = idx & 63;
            sW2T[j * 72 + i] = W2[idx];
        }
        __syncthreads();

        int g   = blockIdx.x * 64 + (tid >> 1);
        int sub = tid & 1;
        if (g >= NW_ITEMS) return;
        int b    = g / (NLINES * 9);
        int rem  = g - b * (NLINES * 9);
        int line = 40 + rem / 9;
        int z    = rem % 9;
        int ki = line / 9 - 4;
        int kj = line % 9 - 4;
        int kk = z - 4;
        const float* iv = &sInv[b * 9];
        float kc0 = TWO_PI * ((float)ki * iv[0] + (float)kj * iv[3] + (float)kk * iv[6]);
        float kc1 = TWO_PI * ((float)ki * iv[1] + (float)kj * iv[4] + (float)kk * iv[7]);
        float kc2 = TWO_PI * ((float)ki * iv[2] + (float)kj * iv[5] + (float)kk * iv[8]);
        float kn = sqrtf(kc0 * kc0 + kc1 * kc1 + kc2 * kc2);

        bool active = (kn > 1e-6f) && !(line == 40 && z < 4);   // half-space mask
        float safe = fmaxf(kn, 1e-6f);
        float x0 = log1pf(safe);
        float f0 = x0, f1 = x0 * x0, f2 = 1.0f / safe;

        // layer 1: full h1 per thread (cheap; avoids exchange)
        u64 h1p[NH / 2];
        #pragma unroll
        for (int j = 0; j < NH; j += 2) {
            float a0 = fmaf(f0, sW1[j],     fmaf(f1, sW1[NH + j],     fmaf(f2, sW1[2 * NH + j],     sB1[j])));
            float a1 = fmaf(f0, sW1[j + 1], fmaf(f1, sW1[NH + j + 1], fmaf(f2, sW1[2 * NH + j + 1], sB1[j + 1])));
            h1p[j >> 1] = pk2(silu(a0), silu(a1));
        }

        // layer 2 + head: this thread handles j in [sub*32, sub*32+32)
        float o_part = 0.0f;
        int j0 = sub * 32;
        for (int jj = 0; jj < 32; jj++) {
            int j = j0 + jj;
            const ulonglong2* wr = (const ulonglong2*)&sW2T[j * 72];
            u64 acc0 = pk2(sB2[j], 0.0f);
            u64 acc1 = 0ULL;
            #pragma unroll
            for (int i2 = 0; i2 < 16; i2++) {
                ulonglong2 wv = wr[i2];
                acc0 = f2fma(h1p[2 * i2],     wv.x, acc0);
                acc1 = f2fma(h1p[2 * i2 + 1], wv.y, acc1);
            }
            float p0, p1, q0, q1;
            upk2(acc0, p0, p1); upk2(acc1, q0, q1);
            float a = (p0 + p1) + (q0 + q1);
            o_part = fmaf(silu(a), sW3[j], o_part);
        }
        // combine pair (lanes 2i <-> 2i+1)
        o_part += __shfl_xor_sync(0xffffffffu, o_part, 1);
        float o = o_part + B3[0];
        float sp = (o > 80.0f) ? o : log1pf(__expf(o));           // softplus
        float w = active ? (FOUR_PI / (safe * safe)) * sp : 0.0f;
        if (sub == 0) g_w[b][line * 9 + z] = w;
    } else {
        // ---------------- phasor role ----------------
        __syncthreads();
        int n = (blockIdx.x - WB) * 128 + tid;
        out[n] = 0.0f;

        int b = batch[n];
        if (n == 0) {
            g_off[0] = 0;
            for (int bb = 1; bb <= b; bb++) g_off[bb] = 0;
        }
        if (n == NN - 1) {
            for (int bb = b + 1; bb <= NB; bb++) g_off[bb] = NN;
        } else {
            int b2 = batch[n + 1];
            for (int bb = b + 1; bb <= b2; bb++) g_off[bb] = n + 1;
        }

        float px = pos[3 * n], py = pos[3 * n + 1], pz = pos[3 * n + 2];
        const float* iv = &sInv[b * 9];
        #pragma unroll
        for (int d = 0; d < 3; d++) {
            float fr = px * iv[d] + py * iv[3 + d] + pz * iv[6 + d];
            float s, c;
            sincosf(TWO_PI * fr, &s, &c);
            float re[9], im[9];
            re[4] = 1.0f; im[4] = 0.0f;
            re[5] = c;    im[5] = s;
            #pragma unroll
            for (int m = 2; m <= 4; m++) {
                re[4 + m] = re[3 + m] * c - im[3 + m] * s;
                im[4 + m] = re[3 + m] * s + im[3 + m] * c;
            }
            #pragma unroll
            for (int m = 1; m <= 4; m++) { re[4 - m] = re[4 + m]; im[4 - m] = -im[4 + m]; }
            #pragma unroll
            for (int mi = 0; mi < 9; mi++) {
                float2 v; v.x = re[mi]; v.y = im[mi];
                g_phas2[d * 9 + mi][n] = v;
            }
        }
    }
}

// ---------------------------------------------------------------------------
// Fused main kernel: 64-thread block per (graph b, half-space line).
// Two warps split the atom range; conj-symmetric phase generation (depth-2
// chain, no Z0 stream). Half-space symmetry factor 2 cancels the 0.5.
// ---------------------------------------------------------------------------
__global__ void __launch_bounds__(64) k_main(const float* __restrict__ source,
                                             float* __restrict__ out)
{
    __shared__ u64 sS[2][36];

    int b    = blockIdx.x;
    int line = 40 + blockIdx.y;
    int w    = threadIdx.x >> 5;
    int lane = threadIdx.x & 31;
    int i4 = line / 9, j4 = line % 9;
    int start = g_off[b], end = g_off[b + 1];

    const float2* __restrict__ PX  = g_phas2[i4];
    const float2* __restrict__ PY  = g_phas2[9 + j4];
    const float2* __restrict__ PZS = g_phas2[23];      // m_z = +1
    const float4* __restrict__ SRC = (const float4*)source;

    u64 acc[36];            // packed (SC, SS) partials, index v = z*4 + c
    #pragma unroll
    for (int v = 0; v < 36; v++) acc[v] = 0ULL;

    // ---- pass 1: structure factors (this warp's atom share) ----
    {
        int a = start + lane + 32 * w;
        float2 LX, LY, LZS; float4 LSV;
        if (a < end) { LX = PX[a]; LY = PY[a]; LZS = PZS[a]; LSV = SRC[a]; }
        while (a < end) {
            float2 X = LX, Y = LY, ZS = LZS; float4 sv = LSV;
            int an = a + 64;
            if (an < end) { LX = PX[an]; LY = PY[an]; LZS = PZS[an]; LSV = SRC[an]; }
            float c1r = X.x * Y.x - X.y * Y.y;
            float c1i = X.x * Y.y + X.y * Y.x;
            u64 P[9];
            build_phases(c1r, c1i, ZS.x, ZS.y, P);
            u64 s0 = pk2(sv.x, sv.x), s1 = pk2(sv.y, sv.y);
            u64 s2 = pk2(sv.z, sv.z), s3 = pk2(sv.w, sv.w);
            #pragma unroll
            for (int z = 0; z < 9; z++) {
                acc[z * 4 + 0] = f2fma(s0, P[z], acc[z * 4 + 0]);
                acc[z * 4 + 1] = f2fma(s1, P[z], acc[z * 4 + 1]);
                acc[z * 4 + 2] = f2fma(s2, P[z], acc[z * 4 + 2]);
                acc[z * 4 + 3] = f2fma(s3, P[z], acc[z * 4 + 3]);
            }
            a = an;
        }
    }

    // ---- distributed exchange reduce on acc[0..31]: lane l ends with value l ----
    #pragma unroll
    for (int o = 16; o >= 1; o >>= 1) {
        bool hi = (lane & o) != 0;
        #pragma unroll
        for (int j = 0; j < o; j++) {
            u64 tlo = shx64(acc[j],     o);
            u64 thi = shx64(acc[j + o], o);
            acc[j] = hi ? f2add(acc[j + o], thi) : f2add(acc[j], tlo);
        }
    }
    sS[w][lane] = acc[0];
    // tail values 32..35 (z=8): full butterfly, all lanes end with totals
    #pragma unroll
    for (int o = 16; o; o >>= 1) {
        acc[32] = f2add(acc[32], shx64(acc[32], o));
        acc[33] = f2add(acc[33], shx64(acc[33], o));
        acc[34] = f2add(acc[34], shx64(acc[34], o));
        acc[35] = f2add(acc[35], shx64(acc[35], o));
    }
    if (lane < 4) {
        u64 qv = (lane == 0) ? acc[32] : (lane == 1) ? acc[33]
               : (lane == 2) ? acc[34] : acc[35];
        sS[w][32 + lane] = qv;
    }
    __syncthreads();

    // ---- combine the two warps + fold in w(k): Wp[v] = wz * (S0[v] + S1[v]) ----
    u64 Wp[36];
    #pragma unroll
    for (int z = 0; z < 9; z++) {
        float wzv = g_w[b][line * 9 + z];
        u64 wzp = pk2(wzv, wzv);
        #pragma unroll
        for (int c = 0; c < 4; c++) {
            int v = z * 4 + c;
            Wp[v] = f2mul(wzp, f2add(sS[0][v], sS[1][v]));
        }
    }
    float hv = g_vinv[b];   // 0.5 (energy) x 2 (half-space) = 1

    // ---- pass 2: per-atom energy from this line's 9 k's ----
    {
        int a = start + lane + 32 * w;
        float2 LX, LY, LZS; float4 LSV;
        if (a < end) { LX = PX[a]; LY = PY[a]; LZS = PZS[a]; LSV = SRC[a]; }
        while (a < end) {
            float2 X = LX, Y = LY, ZS = LZS; float4 sv = LSV;
            int an = a + 64;
            if (an < end) { LX = PX[an]; LY = PY[an]; LZS = PZS[an]; LSV = SRC[an]; }
            float c1r = X.x * Y.x - X.y * Y.y;
            float c1i = X.x * Y.y + X.y * Y.x;
            u64 P[9];
            build_phases(c1r, c1i, ZS.x, ZS.y, P);
            u64 E0 = 0ULL, E1 = 0ULL, E2 = 0ULL, E3 = 0ULL;
            #pragma unroll
            for (int z = 0; z < 9; z++) {
                E0 = f2fma(P[z], Wp[z * 4 + 0], E0);
                E1 = f2fma(P[z], Wp[z * 4 + 1], E1);
                E2 = f2fma(P[z], Wp[z * 4 + 2], E2);
                E3 = f2fma(P[z], Wp[z * 4 + 3], E3);
            }
            float e0a, e0b, e1a, e1b, e2a, e2b, e3a, e3b;
            upk2(E0, e0a, e0b); upk2(E1, e1a, e1b);
            upk2(E2, e2a, e2b); upk2(E3, e3a, e3b);
            float e = sv.x * (e0a + e0b) + sv.y * (e1a + e1b)
                    + sv.z * (e2a + e2b) + sv.w * (e3a + e3b);
            atomicAdd(out + a, hv * e);
            a = an;
        }
    }
}

// ---------------------------------------------------------------------------
extern "C" void kernel_launch(void* const* d_in, const int* in_sizes, int n_in,
                              void* d_out, int out_size)
{
    const float* pos    = (const float*)d_in[0];
    const int*   batch  = (const int*)d_in[1];
    const float* cell   = (const float*)d_in[2];
    const float* source = (const float*)d_in[3];
    const float* W1 = (const float*)d_in[4];
    const float* B1 = (const float*)d_in[5];
    const float* W2 = (const float*)d_in[6];
    const float* B2 = (const float*)d_in[7];
    const float* W3 = (const float*)d_in[8];
    const float* B3 = (const float*)d_in[9];
    float* out = (float*)d_out;

    k_prep<<<WB + PB, 128>>>(pos, batch, cell, W1, B1, W2, B2, W3, B3, out);
    k_main<<<dim3(NB, NLINES), 64>>>(source, out);
}

// round 16
// speedup vs baseline: 1.8396x; 1.0566x over previous
#include <cuda_runtime.h>
#include <math.h>

// Problem constants (fixed by the dataset)
#define NN 8192          // atoms
#define NB 32            // graphs
#define NH 64            // hidden
#define NK 729           // 9^3 lattice points

#define TWO_PI  6.28318530717958647692f
#define FOUR_PI 12.5663706143591729539f

// half-space: lines 40..80 (m_i>0, or m_i==0 && m_j>0, plus (0,0,*) masked to m_z>0)
#define NLINES   41
#define NW_ITEMS (NB * NLINES * 9)          // 11808
#define WB ((NW_ITEMS + 63) / 64)           // 185 MLP blocks (64 items x 2 threads each)
#define ZB (NN / 128)                       // 64 zero/offset blocks

typedef unsigned long long u64;

// -------- device scratch (no allocations allowed) --------
__device__ float g_vinv[NB];
__device__ float g_inv[NB][9];      // inverse cells, o[i*3+d] = inv[i][d]
__device__ int   g_off[NB + 1];
__device__ float g_w[NB][NK];

// ---------------- packed f32x2 helpers ----------------
__device__ __forceinline__ u64 pk2(float lo, float hi) {
    u64 r; asm("mov.b64 %0,{%1,%2};" : "=l"(r) : "f"(lo), "f"(hi)); return r;
}
__device__ __forceinline__ void upk2(u64 v, float& lo, float& hi) {
    asm("mov.b64 {%0,%1},%2;" : "=f"(lo), "=f"(hi) : "l"(v));
}
__device__ __forceinline__ u64 f2fma(u64 a, u64 b, u64 c) {
    u64 d; asm("fma.rn.f32x2 %0,%1,%2,%3;" : "=l"(d) : "l"(a), "l"(b), "l"(c)); return d;
}
__device__ __forceinline__ u64 f2add(u64 a, u64 b) {
    u64 d; asm("add.rn.f32x2 %0,%1,%2;" : "=l"(d) : "l"(a), "l"(b)); return d;
}
__device__ __forceinline__ u64 f2mul(u64 a, u64 b) {
    u64 d; asm("mul.rn.f32x2 %0,%1,%2;" : "=l"(d) : "l"(a), "l"(b)); return d;
}
__device__ __forceinline__ u64 shx64(u64 v, int m) {
    return __shfl_xor_sync(0xffffffffu, v, m);
}

// ---------------------------------------------------------------------------
// 3x3 inverse (double precision). Returns det.
// ---------------------------------------------------------------------------
__device__ __forceinline__ double inv3x3(const float* c, float* o)
{
    double a = c[0], b = c[1], cc = c[2];
    double d = c[3], e = c[4], f  = c[5];
    double g = c[6], h = c[7], i  = c[8];
    double A  = e * i - f * h;
    double Bv = f * g - d * i;
    double C  = d * h - e * g;
    double det = a * A + b * Bv + cc * C;
    double id = 1.0 / det;
    o[0] = (float)(A * id);
    o[1] = (float)((cc * h - b * i) * id);
    o[2] = (float)((b * f - cc * e) * id);
    o[3] = (float)(Bv * id);
    o[4] = (float)((a * i - cc * g) * id);
    o[5] = (float)((cc * d - a * f) * id);
    o[6] = (float)(C * id);
    o[7] = (float)((b * g - a * h) * id);
    o[8] = (float)((a * e - b * d) * id);
    return det;
}

__device__ __forceinline__ float silu(float a) {
    return __fdividef(a, 1.0f + __expf(-a));
}

// ---------------------------------------------------------------------------
// Build the 9 packed phases P[z] = c1 * z^(z-4) from c1 = e^{i*th1} and
// z1 = e^{i*thz}. Chain depth 2; +/-m pairs via conj symmetry, independent.
// ---------------------------------------------------------------------------
__device__ __forceinline__ void build_phases(
    float c1r, float c1i, float z1r, float z1i, u64* P)
{
    float z2r = z1r * z1r - z1i * z1i, z2i = 2.0f * z1r * z1i;
    float z3r = z2r * z1r - z2i * z1i, z3i = fmaf(z2r, z1i, z2i * z1r);
    float z4r = z2r * z2r - z2i * z2i, z4i = 2.0f * z2r * z2i;
    P[4] = pk2(c1r, c1i);
    {
        float t1 = c1r * z1r, t2 = c1i * z1i, t3 = c1r * z1i, t4 = c1i * z1r;
        P[5] = pk2(t1 - t2, t3 + t4);
        P[3] = pk2(t1 + t2, t4 - t3);
    }
    {
        float t1 = c1r * z2r, t2 = c1i * z2i, t3 = c1r * z2i, t4 = c1i * z2r;
        P[6] = pk2(t1 - t2, t3 + t4);
        P[2] = pk2(t1 + t2, t4 - t3);
    }
    {
        float t1 = c1r * z3r, t2 = c1i * z3i, t3 = c1r * z3i, t4 = c1i * z3r;
        P[7] = pk2(t1 - t2, t3 + t4);
        P[1] = pk2(t1 + t2, t4 - t3);
    }
    {
        float t1 = c1r * z4r, t2 = c1i * z4i, t3 = c1r * z4i, t4 = c1i * z4r;
        P[8] = pk2(t1 - t2, t3 + t4);
        P[0] = pk2(t1 + t2, t4 - t3);
    }
}

// ---------------------------------------------------------------------------
// Prep kernel (128 threads). Blocks [0,WB): MLP radial filter, 2 threads per
// item (R15-proven). Blocks [WB,WB+ZB): zero out + batch offsets; block WB
// also publishes g_inv / g_vinv. NO phasor table anymore.
// ---------------------------------------------------------------------------
__global__ void __launch_bounds__(128) k_prep(
    const float* __restrict__ pos, const int* __restrict__ batch,
    const float* __restrict__ cell,
    const float* __restrict__ W1, const float* __restrict__ B1,
    const float* __restrict__ W2, const float* __restrict__ B2,
    const float* __restrict__ W3, const float* __restrict__ B3,
    float* __restrict__ out)
{
    __shared__ float sInv[NB * 9];
    __shared__ __align__(16) float sW2T[NH * 72];   // row j padded to 72 floats
    __shared__ float sW1[3 * NH], sB1[NH], sB2[NH], sW3[NH];

    int tid = threadIdx.x;

    if (blockIdx.x < WB) {
        // ---------------- MLP role: 2 threads per item ----------------
        if (tid < NB) {
            double det = inv3x3(cell + tid * 9, &sInv[tid * 9]);
            if (blockIdx.x == 0) {
                double vol = fabs(det);
                if (vol < 1e-6) vol = 1e-6;
                g_vinv[tid] = (float)(1.0 / vol);
                #pragma unroll
                for (int q = 0; q < 9; q++) g_inv[tid][q] = sInv[tid * 9 + q];
            }
        }
        for (int idx = tid; idx < 3 * NH; idx += 128) sW1[idx] = W1[idx];
        for (int idx = tid; idx < NH; idx += 128) {
            sB1[idx] = B1[idx]; sB2[idx] = B2[idx]; sW3[idx] = W3[idx];
        }
        for (int idx = tid; idx < NH * NH; idx += 128) {
            int i = idx >> 6, j = idx & 63;
            sW2T[j * 72 + i] = W2[idx];
        }
        __syncthreads();

        int g   = blockIdx.x * 64 + (tid >> 1);
        int sub = tid & 1;
        if (g >= NW_ITEMS) return;
        int b    = g / (NLINES * 9);
        int rem  = g - b * (NLINES * 9);
        int line = 40 + rem / 9;
        int z    = rem % 9;
        int ki = line / 9 - 4;
        int kj = line % 9 - 4;
        int kk = z - 4;
        const float* iv = &sInv[b * 9];
        float kc0 = TWO_PI * ((float)ki * iv[0] + (float)kj * iv[3] + (float)kk * iv[6]);
        float kc1 = TWO_PI * ((float)ki * iv[1] + (float)kj * iv[4] + (float)kk * iv[7]);
        float kc2 = TWO_PI * ((float)ki * iv[2] + (float)kj * iv[5] + (float)kk * iv[8]);
        float kn = sqrtf(kc0 * kc0 + kc1 * kc1 + kc2 * kc2);

        bool active = (kn > 1e-6f) && !(line == 40 && z < 4);   // half-space mask
        float safe = fmaxf(kn, 1e-6f);
        float x0 = log1pf(safe);
        float f0 = x0, f1 = x0 * x0, f2 = 1.0f / safe;

        // layer 1: full h1 per thread
        u64 h1p[NH / 2];
        #pragma unroll
        for (int j = 0; j < NH; j += 2) {
            float a0 = fmaf(f0, sW1[j],     fmaf(f1, sW1[NH + j],     fmaf(f2, sW1[2 * NH + j],     sB1[j])));
            float a1 = fmaf(f0, sW1[j + 1], fmaf(f1, sW1[NH + j + 1], fmaf(f2, sW1[2 * NH + j + 1], sB1[j + 1])));
            h1p[j >> 1] = pk2(silu(a0), silu(a1));
        }

        // layer 2 + head: this thread handles j in [sub*32, sub*32+32)
        float o_part = 0.0f;
        int j0 = sub * 32;
        for (int jj = 0; jj < 32; jj++) {
            int j = j0 + jj;
            const ulonglong2* wr = (const ulonglong2*)&sW2T[j * 72];
            u64 acc0 = pk2(sB2[j], 0.0f);
            u64 acc1 = 0ULL;
            #pragma unroll
            for (int i2 = 0; i2 < 16; i2++) {
                ulonglong2 wv = wr[i2];
                acc0 = f2fma(h1p[2 * i2],     wv.x, acc0);
                acc1 = f2fma(h1p[2 * i2 + 1], wv.y, acc1);
            }
            float p0, p1, q0, q1;
            upk2(acc0, p0, p1); upk2(acc1, q0, q1);
            float a = (p0 + p1) + (q0 + q1);
            o_part = fmaf(silu(a), sW3[j], o_part);
        }
        o_part += __shfl_xor_sync(0xffffffffu, o_part, 1);
        float o = o_part + B3[0];
        float sp = (o > 80.0f) ? o : log1pf(__expf(o));           // softplus
        float w = active ? (FOUR_PI / (safe * safe)) * sp : 0.0f;
        if (sub == 0) g_w[b][line * 9 + z] = w;
    } else {
        // ---------------- zero / offsets role ----------------
        int n = (blockIdx.x - WB) * 128 + tid;
        out[n] = 0.0f;

        int b = batch[n];
        if (n == 0) {
            g_off[0] = 0;
            for (int bb = 1; bb <= b; bb++) g_off[bb] = 0;
        }
        if (n == NN - 1) {
            for (int bb = b + 1; bb <= NB; bb++) g_off[bb] = NN;
        } else {
            int b2 = batch[n + 1];
            for (int bb = b + 1; bb <= b2; bb++) g_off[bb] = n + 1;
        }
    }
}

// ---------------------------------------------------------------------------
// Fused main kernel: 64-thread block per (graph b, half-space line).
// Phases computed ON THE FLY: th1 = pos.u (block-constant u folds the (mi,mj)
// lattice indices into the inverse cell), thz = pos.v; 2x __sincosf/atom.
// No phasor table, single pos+source load stream.
// Half-space symmetry factor 2 cancels the 0.5.
// ---------------------------------------------------------------------------
__global__ void __launch_bounds__(64) k_main(const float* __restrict__ pos,
                                             const float* __restrict__ source,
                                             float* __restrict__ out)
{
    __shared__ u64 sS[2][36];

    int b    = blockIdx.x;
    int line = 40 + blockIdx.y;
    int w    = threadIdx.x >> 5;
    int lane = threadIdx.x & 31;
    int i4 = line / 9, j4 = line % 9;
    int start = g_off[b], end = g_off[b + 1];

    // block-constant direction vectors
    float mi = (float)(i4 - 4), mj = (float)(j4 - 4);
    const float* iv = g_inv[b];
    float u0 = TWO_PI * (mi * iv[0] + mj * iv[1]);
    float u1 = TWO_PI * (mi * iv[3] + mj * iv[4]);
    float u2 = TWO_PI * (mi * iv[6] + mj * iv[7]);
    float v0 = TWO_PI * iv[2], v1 = TWO_PI * iv[5], v2 = TWO_PI * iv[8];

    const float4* __restrict__ SRC = (const float4*)source;

    u64 acc[36];            // packed (SC, SS) partials, index v = z*4 + c
    #pragma unroll
    for (int v = 0; v < 36; v++) acc[v] = 0ULL;

    // ---- pass 1: structure factors (this warp's atom share) ----
    {
        int a = start + lane + 32 * w;
        float Lx, Ly, Lz; float4 LSV;
        if (a < end) {
            Lx = __ldg(pos + 3 * a); Ly = __ldg(pos + 3 * a + 1); Lz = __ldg(pos + 3 * a + 2);
            LSV = SRC[a];
        }
        while (a < end) {
            float px = Lx, py = Ly, pz = Lz; float4 sv = LSV;
            int an = a + 64;
            if (an < end) {
                Lx = __ldg(pos + 3 * an); Ly = __ldg(pos + 3 * an + 1); Lz = __ldg(pos + 3 * an + 2);
                LSV = SRC[an];
            }
            float th1 = fmaf(px, u0, fmaf(py, u1, pz * u2));
            float thz = fmaf(px, v0, fmaf(py, v1, pz * v2));
            float c1r, c1i, z1r, z1i;
            __sincosf(th1, &c1i, &c1r);
            __sincosf(thz, &z1i, &z1r);
            u64 P[9];
            build_phases(c1r, c1i, z1r, z1i, P);
            u64 s0 = pk2(sv.x, sv.x), s1 = pk2(sv.y, sv.y);
            u64 s2 = pk2(sv.z, sv.z), s3 = pk2(sv.w, sv.w);
            #pragma unroll
            for (int z = 0; z < 9; z++) {
                acc[z * 4 + 0] = f2fma(s0, P[z], acc[z * 4 + 0]);
                acc[z * 4 + 1] = f2fma(s1, P[z], acc[z * 4 + 1]);
                acc[z * 4 + 2] = f2fma(s2, P[z], acc[z * 4 + 2]);
                acc[z * 4 + 3] = f2fma(s3, P[z], acc[z * 4 + 3]);
            }
            a = an;
        }
    }

    // ---- distributed exchange reduce on acc[0..31]: lane l ends with value l ----
    #pragma unroll
    for (int o = 16; o >= 1; o >>= 1) {
        bool hi = (lane & o) != 0;
        #pragma unroll
        for (int j = 0; j < o; j++) {
            u64 tlo = shx64(acc[j],     o);
            u64 thi = shx64(acc[j + o], o);
            acc[j] = hi ? f2add(acc[j + o], thi) : f2add(acc[j], tlo);
        }
    }
    sS[w][lane] = acc[0];
    // tail values 32..35 (z=8): full butterfly, all lanes end with totals
    #pragma unroll
    for (int o = 16; o; o >>= 1) {
        acc[32] = f2add(acc[32], shx64(acc[32], o));
        acc[33] = f2add(acc[33], shx64(acc[33], o));
        acc[34] = f2add(acc[34], shx64(acc[34], o));
        acc[35] = f2add(acc[35], shx64(acc[35], o));
    }
    if (lane < 4) {
        u64 qv = (lane == 0) ? acc[32] : (lane == 1) ? acc[33]
               : (lane == 2) ? acc[34] : acc[35];
        sS[w][32 + lane] = qv;
    }
    __syncthreads();

    // ---- combine the two warps + fold in w(k): Wp[v] = wz * (S0[v] + S1[v]) ----
    u64 Wp[36];
    #pragma unroll
    for (int z = 0; z < 9; z++) {
        float wzv = g_w[b][line * 9 + z];
        u64 wzp = pk2(wzv, wzv);
        #pragma unroll
        for (int c = 0; c < 4; c++) {
            int v = z * 4 + c;
            Wp[v] = f2mul(wzp, f2add(sS[0][v], sS[1][v]));
        }
    }
    float hv = g_vinv[b];   // 0.5 (energy) x 2 (half-space) = 1

    // ---- pass 2: per-atom energy from this line's 9 k's ----
    {
        int a = start + lane + 32 * w;
        float Lx, Ly, Lz; float4 LSV;
        if (a < end) {
            Lx = __ldg(pos + 3 * a); Ly = __ldg(pos + 3 * a + 1); Lz = __ldg(pos + 3 * a + 2);
            LSV = SRC[a];
        }
        while (a < end) {
            float px = Lx, py = Ly, pz = Lz; float4 sv = LSV;
            int an = a + 64;
            if (an < end) {
                Lx = __ldg(pos + 3 * an); Ly = __ldg(pos + 3 * an + 1); Lz = __ldg(pos + 3 * an + 2);
                LSV = SRC[an];
            }
            float th1 = fmaf(px, u0, fmaf(py, u1, pz * u2));
            float thz = fmaf(px, v0, fmaf(py, v1, pz * v2));
            float c1r, c1i, z1r, z1i;
            __sincosf(th1, &c1i, &c1r);
            __sincosf(thz, &z1i, &z1r);
            u64 P[9];
            build_phases(c1r, c1i, z1r, z1i, P);
            u64 E0 = 0ULL, E1 = 0ULL, E2 = 0ULL, E3 = 0ULL;
            #pragma unroll
            for (int z = 0; z < 9; z++) {
                E0 = f2fma(P[z], Wp[z * 4 + 0], E0);
                E1 = f2fma(P[z], Wp[z * 4 + 1], E1);
                E2 = f2fma(P[z], Wp[z * 4 + 2], E2);
                E3 = f2fma(P[z], Wp[z * 4 + 3], E3);
            }
            float e0a, e0b, e1a, e1b, e2a, e2b, e3a, e3b;
            upk2(E0, e0a, e0b); upk2(E1, e1a, e1b);
            upk2(E2, e2a, e2b); upk2(E3, e3a, e3b);
            float e = sv.x * (e0a + e0b) + sv.y * (e1a + e1b)
                    + sv.z * (e2a + e2b) + sv.w * (e3a + e3b);
            atomicAdd(out + a, hv * e);
            a = an;
        }
    }
}

// ---------------------------------------------------------------------------
extern "C" void kernel_launch(void* const* d_in, const int* in_sizes, int n_in,
                              void* d_out, int out_size)
{
    const float* pos    = (const float*)d_in[0];
    const int*   batch  = (const int*)d_in[1];
    const float* cell   = (const float*)d_in[2];
    const float* source = (const float*)d_in[3];
    const float* W1 = (const float*)d_in[4];
    const float* B1 = (const float*)d_in[5];
    const float* W2 = (const float*)d_in[6];
    const float* B2 = (const float*)d_in[7];
    const float* W3 = (const float*)d_in[8];
    const float* B3 = (const float*)d_in[9];
    float* out = (float*)d_out;

    k_prep<<<WB + ZB, 128>>>(pos, batch, cell, W1, B1, W2, B2, W3, B3, out);
    k_main<<<dim3(NB, NLINES), 64>>>(pos, source, out);
}